// round 3
// baseline (speedup 1.0000x reference)
#include <cuda_runtime.h>
#include <math.h>
#include <stdint.h>

#define H        4096
#define E        64
#define TM       64      // tokens per block
#define TK       32      // k-chunk
#define NTHREADS 256
#define XD       132     // xs_dup row stride in floats (128 data + 4 pad, 16B-aligned rows)
#define WD       68      // ws row stride in floats

// out layout (fp32, concatenated): probs[ntok][64] | top_k_weights[ntok][2] | top_k_index[ntok][2]

__global__ __launch_bounds__(NTHREADS, 2)
void router_kernel(const float* __restrict__ xg,
                   const float* __restrict__ wg,
                   const float* __restrict__ sg,
                   const float* __restrict__ pes,
                   float* __restrict__ out,
                   int ntok)
{
    // xs_dup: [TK][2*TM] dup-packed tokens, stride XD. ws: [TK][E], stride WD.
    __shared__ float smem[TK * XD + TK * WD];   // 4224 + 2176 = 6400 floats
    __shared__ float ssq[TM];
    __shared__ float sums[TM];
    __shared__ float topw[TM * 2];
    __shared__ float topi[TM * 2];

    float* xsd = smem;                 // dup x tile
    float* wsp = smem + TK * XD;       // w tile

    const uint32_t sx_base = (uint32_t)__cvta_generic_to_shared(xsd);
    const uint32_t sw_base = (uint32_t)__cvta_generic_to_shared(wsp);

    const int tid = threadIdx.x;
    const int tg  = tid >> 4;      // 0..15 : token group (4 tokens)
    const int eg  = tid & 15;      // 0..15 : expert group (4 experts)
    const int tok0 = blockIdx.x * TM;

    if (tid < TM) ssq[tid] = 0.f;

    // tile-load assignment (same as passing kernel)
    const int rowA = tid >> 3;     // 0..31
    const int kqA  = tid & 7;      // float4 slot within 32-wide k chunk

    const float* xA = xg + (size_t)(tok0 + rowA) * H + kqA * 4;
    const float* xB = xA + (size_t)32 * H;
    const float* wA = wg + (size_t)rowA * H + kqA * 4;   // expert row = rowA
    const float* wB = wA + (size_t)32 * H;
    const float* sA = sg + kqA * 4;

    float ssqA = 0.f, ssqB = 0.f;

    // prologue prefetch (chunk 0)
    float4 xr0 = *(const float4*)xA;
    float4 xr1 = *(const float4*)xB;
    float4 wr0 = *(const float4*)wA;
    float4 wr1 = *(const float4*)wB;
    float4 sr  = *(const float4*)sA;

    // packed accumulators: acc[i][p] holds (token tg*4+i) x (experts eg*4+2p, +2p+1)
    uint64_t acc[4][2];
    #pragma unroll
    for (int i = 0; i < 4; i++) { acc[i][0] = 0ull; acc[i][1] = 0ull; }

    const uint32_t ax0 = sx_base + (uint32_t)(tg * 8) * 4;   // 4 dup tokens = 32B
    const uint32_t aw0 = sw_base + (uint32_t)(eg * 4) * 4;   // 4 experts = 16B

    const int NC = H / TK;   // 128
    for (int c = 0; c < NC; c++) {
        // ---- store prefetched tile to smem; x duplicated (STS.64 {v,v}),
        //      fold elementwise scale into W, accumulate raw-x sum of squares
        const int kb = kqA * 4;
        {
            const uint32_t bx = sx_base + (uint32_t)(2 * rowA) * 4;
            #define STDUP(kk, tt, vv) \
                asm volatile("st.shared.v2.f32 [%0], {%1, %1};" :: \
                    "r"(bx + (uint32_t)((kk) * XD + 2 * (tt)) * 4), "f"(vv));
            STDUP(kb + 0, 0,  xr0.x); STDUP(kb + 1, 0,  xr0.y);
            STDUP(kb + 2, 0,  xr0.z); STDUP(kb + 3, 0,  xr0.w);
            STDUP(kb + 0, 32, xr1.x); STDUP(kb + 1, 32, xr1.y);
            STDUP(kb + 2, 32, xr1.z); STDUP(kb + 3, 32, xr1.w);
            #undef STDUP
        }
        wsp[(kb + 0) * WD + rowA] = wr0.x * sr.x;  wsp[(kb + 1) * WD + rowA] = wr0.y * sr.y;
        wsp[(kb + 2) * WD + rowA] = wr0.z * sr.z;  wsp[(kb + 3) * WD + rowA] = wr0.w * sr.w;
        wsp[(kb + 0) * WD + rowA + 32] = wr1.x * sr.x;  wsp[(kb + 1) * WD + rowA + 32] = wr1.y * sr.y;
        wsp[(kb + 2) * WD + rowA + 32] = wr1.z * sr.z;  wsp[(kb + 3) * WD + rowA + 32] = wr1.w * sr.w;

        ssqA += xr0.x*xr0.x + xr0.y*xr0.y + xr0.z*xr0.z + xr0.w*xr0.w;
        ssqB += xr1.x*xr1.x + xr1.y*xr1.y + xr1.z*xr1.z + xr1.w*xr1.w;

        __syncthreads();

        // ---- prefetch next chunk
        if (c + 1 < NC) {
            const int off = (c + 1) * TK;
            xr0 = *(const float4*)(xA + off);
            xr1 = *(const float4*)(xB + off);
            wr0 = *(const float4*)(wA + off);
            wr1 = *(const float4*)(wB + off);
            sr  = *(const float4*)(sA + off);
        }

        // ---- compute: 32 k-steps, each 3x LDS.128 + 8x fma.rn.f32x2 (= 64 FMA lanes)
        #pragma unroll
        for (int kk = 0; kk < TK; kk++) {
            uint64_t xp0, xp1, xp2, xp3, wp0, wp1;
            asm volatile("ld.shared.v2.b64 {%0, %1}, [%2];"
                         : "=l"(xp0), "=l"(xp1)
                         : "r"(ax0 + (uint32_t)(kk * XD * 4)));
            asm volatile("ld.shared.v2.b64 {%0, %1}, [%2];"
                         : "=l"(xp2), "=l"(xp3)
                         : "r"(ax0 + (uint32_t)(kk * XD * 4 + 16)));
            asm volatile("ld.shared.v2.b64 {%0, %1}, [%2];"
                         : "=l"(wp0), "=l"(wp1)
                         : "r"(aw0 + (uint32_t)(kk * WD * 4)));
            asm("fma.rn.f32x2 %0, %1, %2, %0;" : "+l"(acc[0][0]) : "l"(xp0), "l"(wp0));
            asm("fma.rn.f32x2 %0, %1, %2, %0;" : "+l"(acc[0][1]) : "l"(xp0), "l"(wp1));
            asm("fma.rn.f32x2 %0, %1, %2, %0;" : "+l"(acc[1][0]) : "l"(xp1), "l"(wp0));
            asm("fma.rn.f32x2 %0, %1, %2, %0;" : "+l"(acc[1][1]) : "l"(xp1), "l"(wp1));
            asm("fma.rn.f32x2 %0, %1, %2, %0;" : "+l"(acc[2][0]) : "l"(xp2), "l"(wp0));
            asm("fma.rn.f32x2 %0, %1, %2, %0;" : "+l"(acc[2][1]) : "l"(xp2), "l"(wp1));
            asm("fma.rn.f32x2 %0, %1, %2, %0;" : "+l"(acc[3][0]) : "l"(xp3), "l"(wp0));
            asm("fma.rn.f32x2 %0, %1, %2, %0;" : "+l"(acc[3][1]) : "l"(xp3), "l"(wp1));
        }
        __syncthreads();
    }

    // ---- reduce sum of squares (8 partial owners per token)
    atomicAdd(&ssq[rowA],      ssqA);
    atomicAdd(&ssq[rowA + 32], ssqB);

    // ---- scores to smem (overlays the tiles; last sync above protects reads)
    float* sc = smem;   // sc[t][e], stride 64, 4096 floats (fits in 6400)
    #pragma unroll
    for (int i = 0; i < 4; i++) {
        float2 a0, a1;
        a0 = *reinterpret_cast<float2*>(&acc[i][0]);
        a1 = *reinterpret_cast<float2*>(&acc[i][1]);
        float4 v = make_float4(a0.x, a0.y, a1.x, a1.y);
        *(float4*)&sc[(tg * 4 + i) * 64 + eg * 4] = v;
    }
    __syncthreads();

    // ---- per-token softmax + top-2 (one thread per token)
    if (tid < TM) {
        const int t = tid;
        const float r = 1.0f / (64.0f * sqrtf(ssq[t] * (1.0f / 4096.0f) + 1e-6f));
        float m = -1e30f;
        #pragma unroll 8
        for (int e = 0; e < 64; e++) m = fmaxf(m, sc[t * 64 + e] * r);
        float sum = 0.f;
        float m1 = -1.f, m2 = -1.f;
        int   i1 = 0,   i2 = 0;
        for (int e = 0; e < 64; e++) {
            float ex = __expf(sc[t * 64 + e] * r - m);
            sum += ex;
            sc[t * 64 + e] = ex;
            if (ex > m1)      { m2 = m1; i2 = i1; m1 = ex; i1 = e; }
            else if (ex > m2) { m2 = ex; i2 = e; }
        }
        sums[t] = sum;
        const float denom = 1.0f / (m1 + m2);
        topw[t * 2 + 0] = m1 * denom * pes[i1];
        topw[t * 2 + 1] = m2 * denom * pes[i2];
        topi[t * 2 + 0] = (float)i1;
        topi[t * 2 + 1] = (float)i2;
    }
    __syncthreads();

    // ---- coalesced outputs
    float* pout = out + (size_t)tok0 * 64;
    #pragma unroll
    for (int q = 0; q < 4; q++) {
        const int idx = tid + q * 256;          // float4 index, 1024 total
        float4 v = *(const float4*)&sc[idx * 4];
        const float inv = 1.0f / sums[idx >> 4];
        v.x *= inv; v.y *= inv; v.z *= inv; v.w *= inv;
        *(float4*)&pout[idx * 4] = v;
    }
    float* wout = out + (size_t)ntok * 64;
    float* iout = wout + (size_t)ntok * 2;
    if (tid < TM * 2) {
        wout[tok0 * 2 + tid] = topw[tid];
        iout[tok0 * 2 + tid] = topi[tid];
    }
}

extern "C" void kernel_launch(void* const* d_in, const int* in_sizes, int n_in,
                              void* d_out, int out_size)
{
    (void)n_in; (void)out_size;
    const float* x   = (const float*)d_in[0];
    const float* w   = (const float*)d_in[1];
    const float* s   = (const float*)d_in[2];
    const float* pes = (const float*)d_in[3];
    const int ntok = in_sizes[0] / H;           // 16384
    const int grid = ntok / TM;                 // 256
    router_kernel<<<grid, NTHREADS>>>(x, w, s, pes, (float*)d_out, ntok);
}

// round 5
// speedup vs baseline: 2.9869x; 2.9869x over previous
#include <cuda_runtime.h>
#include <cuda_bf16.h>
#include <math.h>
#include <stdint.h>

#define H        4096
#define E        64
#define TM       64               // tokens per block
#define KC       64               // k per chunk
#define NC       (H / KC)         // 64
#define NTHREADS 256

// dynamic smem (bytes): X limbs [buf][limb] 64x128B, then W limbs same
#define XB(buf, limb) (((buf) << 14) + ((limb) << 13))
#define WOFF 32768
#define WB(buf, limb) (WOFF + ((buf) << 14) + ((limb) << 13))
#define SMEM_BYTES 65536

// W limbs (scale folded), [limb][expert*512 + k/8], 16B-aligned for cp.async
__device__ uint4 g_wl[2][E * (H / 8)];

static __device__ __forceinline__ void split2(float x, float y, uint32_t& hi, uint32_t& lo) {
    asm("cvt.rn.bf16x2.f32 %0, %1, %2;" : "=r"(hi) : "f"(y), "f"(x));   // low16 = bf16(x)
    const float hx = __uint_as_float(hi << 16);
    const float hy = __uint_as_float(hi & 0xFFFF0000u);
    const float rx = x - hx, ry = y - hy;
    asm("cvt.rn.bf16x2.f32 %0, %1, %2;" : "=r"(lo) : "f"(ry), "f"(rx));
}

__global__ void wprep_kernel(const float* __restrict__ wg, const float* __restrict__ sg)
{
    const int e = blockIdx.x;
    const int t = threadIdx.x;
    #pragma unroll
    for (int i = 0; i < 2; i++) {
        const int u = t + 256 * i;          // uint4 index within row (0..511) = 8 floats
        const float4 wA = ((const float4*)(wg + (size_t)e * H))[u * 2];
        const float4 wB = ((const float4*)(wg + (size_t)e * H))[u * 2 + 1];
        const float4 sA = ((const float4*)sg)[u * 2];
        const float4 sB = ((const float4*)sg)[u * 2 + 1];
        float4 a = wA, b = wB;
        a.x *= sA.x; a.y *= sA.y; a.z *= sA.z; a.w *= sA.w;
        b.x *= sB.x; b.y *= sB.y; b.z *= sB.z; b.w *= sB.w;
        uint32_t h0, l0, h1, l1, h2, l2, h3, l3;
        split2(a.x, a.y, h0, l0);  split2(a.z, a.w, h1, l1);
        split2(b.x, b.y, h2, l2);  split2(b.z, b.w, h3, l3);
        g_wl[0][e * 512 + u] = make_uint4(h0, h1, h2, h3);
        g_wl[1][e * 512 + u] = make_uint4(l0, l1, l2, l3);
    }
}

#define LDSM4(r0, r1, r2, r3, addr) \
    asm volatile("ldmatrix.sync.aligned.m8n8.x4.shared.b16 {%0,%1,%2,%3}, [%4];" \
                 : "=r"(r0), "=r"(r1), "=r"(r2), "=r"(r3) : "r"(addr))

#define MMA(acc, a, b0, b1) \
    asm volatile("mma.sync.aligned.m16n8k16.row.col.f32.bf16.bf16.f32 " \
                 "{%0,%1,%2,%3},{%4,%5,%6,%7},{%8,%9},{%0,%1,%2,%3};" \
                 : "+f"((acc)[0]), "+f"((acc)[1]), "+f"((acc)[2]), "+f"((acc)[3]) \
                 : "r"((a)[0]), "r"((a)[1]), "r"((a)[2]), "r"((a)[3]), "r"(b0), "r"(b1))

#define STS128(addr, v0, v1, v2, v3) \
    asm volatile("st.shared.v4.b32 [%0], {%1,%2,%3,%4};" \
                 :: "r"(addr), "r"(v0), "r"(v1), "r"(v2), "r"(v3))

#define CPASYNC16(dst, src) \
    asm volatile("cp.async.ca.shared.global [%0], [%1], 16;" :: "r"(dst), "l"(src))

// out layout (fp32): probs[ntok][64] | top_k_weights[ntok][2] | top_k_index[ntok][2]

__global__ __launch_bounds__(NTHREADS, 2)
void router_kernel(const float* __restrict__ xg, const float* __restrict__ pes,
                   float* __restrict__ out, int ntok)
{
    extern __shared__ char smem[];
    __shared__ float ssq[TM];
    __shared__ float topw[TM * 2];
    __shared__ float topi[TM * 2];

    uint32_t sb;
    asm("{ .reg .u64 t; cvta.to.shared.u64 t, %1; cvt.u32.u64 %0, t; }" : "=r"(sb) : "l"(smem));

    const int tid  = threadIdx.x;
    const int tok0 = blockIdx.x * TM;
    if (tid < TM) ssq[tid] = 0.f;

    // ---- X load/convert assignment: row r (0..63), p = quarter of row
    const int r = tid >> 2;
    const int p = tid & 3;
    const float* xrow = xg + (size_t)(tok0 + r) * H;
    float ssql = 0.f;

    // ---- W cp.async assignment: limb wl, expert row wr, chunks wc0..wc0+3
    const int wl  = tid >> 7;
    const int wr  = (tid >> 1) & 63;
    const int wc0 = (tid & 1) * 4;
    const char* wsrc_base = (const char*)&g_wl[wl][wr * 512];   // 8192 B per expert row
    const uint32_t wxor = (uint32_t)(wr & 7);

    // ---- mma fragment addressing (per-thread constants)
    const int lane = tid & 31;
    const int wid  = tid >> 5;
    const int m0 = (wid >> 1) << 4;            // 0,16,32,48
    const int n0 = (wid & 1) << 5;             // 0,32
    const int arow = m0 + (lane & 15);
    const int apar = lane >> 4;
    const int axor = arow & 7;
    const int brow0 = n0 + (lane & 7) + ((lane >> 4) << 3);
    const int brow1 = brow0 + 16;
    const int bpar  = (lane >> 3) & 1;

    float acc[4][4];
    #pragma unroll
    for (int i = 0; i < 4; i++)
        #pragma unroll
        for (int j = 0; j < 4; j++) acc[i][j] = 0.f;

    // ---- prologue: W chunk0 cp.async, X chunk0 LDG
    {
        const uint32_t wdst = sb + WB(0, wl) + (uint32_t)wr * 128;
        #pragma unroll
        for (int j = 0; j < 4; j++) {
            const uint32_t cc = (uint32_t)(wc0 + j);
            CPASYNC16(wdst + ((cc ^ wxor) << 4), wsrc_base + cc * 16);
        }
        asm volatile("cp.async.commit_group;" ::: "memory");
    }
    float4 x0 = *(const float4*)(xrow + 8 * p);
    float4 x1 = *(const float4*)(xrow + 8 * p + 4);
    float4 x2 = *(const float4*)(xrow + 8 * p + 32);
    float4 x3 = *(const float4*)(xrow + 8 * p + 36);

    for (int c = 0; c < NC; c++) {
        const int buf = c & 1;

        // ---- sumsq + split + STS X chunk c
        ssql += x0.x*x0.x + x0.y*x0.y + x0.z*x0.z + x0.w*x0.w
              + x1.x*x1.x + x1.y*x1.y + x1.z*x1.z + x1.w*x1.w
              + x2.x*x2.x + x2.y*x2.y + x2.z*x2.z + x2.w*x2.w
              + x3.x*x3.x + x3.y*x3.y + x3.z*x3.z + x3.w*x3.w;
        {
            uint32_t h0,l0,h1,l1,h2,l2,h3,l3,h4,l4,h5,l5,h6,l6,h7,l7;
            split2(x0.x, x0.y, h0, l0);  split2(x0.z, x0.w, h1, l1);
            split2(x1.x, x1.y, h2, l2);  split2(x1.z, x1.w, h3, l3);
            split2(x2.x, x2.y, h4, l4);  split2(x2.z, x2.w, h5, l5);
            split2(x3.x, x3.y, h6, l6);  split2(x3.z, x3.w, h7, l7);
            const uint32_t rb = sb + XB(buf, 0) + (uint32_t)r * 128;
            const uint32_t d0 = rb + (uint32_t)((p       ^ (r & 7)) << 4);
            const uint32_t d1 = rb + (uint32_t)(((p + 4) ^ (r & 7)) << 4);
            STS128(d0,        h0, h1, h2, h3);
            STS128(d0 + 8192, l0, l1, l2, l3);
            STS128(d1,        h4, h5, h6, h7);
            STS128(d1 + 8192, l4, l5, l6, l7);
        }

        // ---- prefetch X chunk c+1
        if (c + 1 < NC) {
            const size_t k2 = (size_t)(c + 1) * KC;
            x0 = *(const float4*)(xrow + k2 + 8 * p);
            x1 = *(const float4*)(xrow + k2 + 8 * p + 4);
            x2 = *(const float4*)(xrow + k2 + 8 * p + 32);
            x3 = *(const float4*)(xrow + k2 + 8 * p + 36);
        }

        asm volatile("cp.async.wait_group 0;" ::: "memory");
        __syncthreads();

        // ---- issue W chunk c+1 into buf^1 (safe: all warps past mma of c-1)
        if (c + 1 < NC) {
            const uint32_t wdst = sb + WB(buf ^ 1, wl) + (uint32_t)wr * 128;
            const char* ws = wsrc_base + (size_t)(c + 1) * 128;   // KC*2 bytes
            #pragma unroll
            for (int j = 0; j < 4; j++) {
                const uint32_t cc = (uint32_t)(wc0 + j);
                CPASYNC16(wdst + ((cc ^ wxor) << 4), ws + cc * 16);
            }
            asm volatile("cp.async.commit_group;" ::: "memory");
        }

        // ---- mma chunk c: 4 k-steps x (2 limbs A/B ldmatrix + 12 HMMA)
        #pragma unroll
        for (int ks = 0; ks < 4; ks++) {
            uint32_t A[2][4], B[2][8];
            #pragma unroll
            for (int limb = 0; limb < 2; limb++) {
                const uint32_t xbase = sb + XB(buf, limb);
                const uint32_t wbase = sb + WB(buf, limb);
                const uint32_t aaddr = xbase + (uint32_t)arow * 128
                                     + (uint32_t)((((ks << 1) + apar) ^ axor) << 4);
                const uint32_t b0a = wbase + (uint32_t)brow0 * 128
                                   + (uint32_t)((((ks << 1) + bpar) ^ (brow0 & 7)) << 4);
                const uint32_t b1a = wbase + (uint32_t)brow1 * 128
                                   + (uint32_t)((((ks << 1) + bpar) ^ (brow1 & 7)) << 4);
                LDSM4(A[limb][0], A[limb][1], A[limb][2], A[limb][3], aaddr);
                LDSM4(B[limb][0], B[limb][1], B[limb][2], B[limb][3], b0a);
                LDSM4(B[limb][4], B[limb][5], B[limb][6], B[limb][7], b1a);
            }
            #pragma unroll
            for (int nt = 0; nt < 4; nt++) {
                MMA(acc[nt], A[0], B[0][nt * 2], B[0][nt * 2 + 1]);   // hi*hi
                MMA(acc[nt], A[0], B[1][nt * 2], B[1][nt * 2 + 1]);   // hi*lo
                MMA(acc[nt], A[1], B[0][nt * 2], B[0][nt * 2 + 1]);   // lo*hi
            }
        }
    }

    atomicAdd(&ssq[r], ssql);
    __syncthreads();

    // ---- dump accumulators to padded score tile sc[64][68]
    float* sc = (float*)smem;
    {
        const int row0 = m0 + (lane >> 2);
        const int colb = n0 + (lane & 3) * 2;
        #pragma unroll
        for (int nt = 0; nt < 4; nt++) {
            const int col = colb + nt * 8;
            sc[row0 * 68 + col]       = acc[nt][0];
            sc[row0 * 68 + col + 1]   = acc[nt][1];
            sc[(row0 + 8) * 68 + col]     = acc[nt][2];
            sc[(row0 + 8) * 68 + col + 1] = acc[nt][3];
        }
    }
    __syncthreads();

    // ---- per-token RMSNorm factor + softmax + top-2
    if (tid < TM) {
        const int t = tid;
        const float rr = 1.0f / (64.0f * sqrtf(ssq[t] * (1.0f / 4096.0f) + 1e-6f));
        float m = -1e30f;
        #pragma unroll 8
        for (int e = 0; e < E; e++) m = fmaxf(m, sc[t * 68 + e] * rr);
        float sum = 0.f, m1 = -1.f, m2 = -1.f;
        int i1 = 0, i2 = 0;
        for (int e = 0; e < E; e++) {
            const float ex = __expf(sc[t * 68 + e] * rr - m);
            sum += ex;
            sc[t * 68 + e] = ex;
            if (ex > m1)      { m2 = m1; i2 = i1; m1 = ex; i1 = e; }
            else if (ex > m2) { m2 = ex; i2 = e; }
        }
        const float inv = 1.0f / sum;
        #pragma unroll 8
        for (int e = 0; e < E; e++) sc[t * 68 + e] *= inv;
        const float dn = 1.0f / (m1 + m2);
        topw[t * 2 + 0] = m1 * dn * pes[i1];
        topw[t * 2 + 1] = m2 * dn * pes[i2];
        topi[t * 2 + 0] = (float)i1;
        topi[t * 2 + 1] = (float)i2;
    }
    __syncthreads();

    // ---- outputs
    float* pout = out + (size_t)tok0 * 64;
    #pragma unroll
    for (int j = 0; j < 4; j++) {
        const int q = p + 4 * j;
        *(float4*)&pout[r * 64 + q * 4] = *(const float4*)&sc[r * 68 + q * 4];
    }
    float* wout = out + (size_t)ntok * 64;
    float* iout = wout + (size_t)ntok * 2;
    if (tid < TM * 2) {
        wout[tok0 * 2 + tid] = topw[tid];
        iout[tok0 * 2 + tid] = topi[tid];
    }
}

extern "C" void kernel_launch(void* const* d_in, const int* in_sizes, int n_in,
                              void* d_out, int out_size)
{
    (void)n_in; (void)out_size;
    const float* x   = (const float*)d_in[0];
    const float* w   = (const float*)d_in[1];
    const float* s   = (const float*)d_in[2];
    const float* pes = (const float*)d_in[3];
    const int ntok = in_sizes[0] / H;            // 16384
    wprep_kernel<<<E, 256>>>(w, s);
    cudaFuncSetAttribute(router_kernel, cudaFuncAttributeMaxDynamicSharedMemorySize, SMEM_BYTES);
    router_kernel<<<ntok / TM, NTHREADS, SMEM_BYTES>>>(x, pes, (float*)d_out, ntok);
}